// round 2
// baseline (speedup 1.0000x reference)
#include <cuda_runtime.h>

// Problem constants (fixed shapes from setup_inputs)
#define N_NODES 4096
#define B_SZ 16
#define P_SZ 4
#define D_IN 128
#define E_DIM 192
#define D_MODEL 128
#define K_FEAT 384   // 3 * D_IN
#define K_TOT 576    // K_FEAT + E_DIM

typedef unsigned long long ull;

// ---- packed f32x2 helpers (Blackwell sm_100+) ----
__device__ __forceinline__ ull pack2(float x) {
    ull r;
    asm("mov.b64 %0, {%1, %1};" : "=l"(r) : "f"(x));
    return r;
}
__device__ __forceinline__ ull pack2f(float x, float y) {
    ull r;
    asm("mov.b64 %0, {%1, %2};" : "=l"(r) : "f"(x), "f"(y));
    return r;
}
__device__ __forceinline__ void fma2(ull &d, ull a, ull b) {
    asm("fma.rn.f32x2 %0, %1, %2, %0;" : "+l"(d) : "l"(a), "l"(b));
}
__device__ __forceinline__ float2 unpack2(ull v) {
    float2 r;
    asm("mov.b64 {%0, %1}, %2;" : "=f"(r.x), "=f"(r.y) : "l"(v));
    return r;
}

// ---------------------------------------------------------------------------
// Kernel 1: adj passthrough copy (vectorized)
// ---------------------------------------------------------------------------
__global__ void copy_kernel(const float4* __restrict__ src, float4* __restrict__ dst, int n4) {
    int i = blockIdx.x * blockDim.x + threadIdx.x;
    if (i < n4) dst[i] = src[i];
}

// ---------------------------------------------------------------------------
// Kernel 2: m[p,n] = max over window-3 of zero-padded mask
// ---------------------------------------------------------------------------
__global__ void mask_kernel(const float* __restrict__ mask, float* __restrict__ m_out) {
    int i = blockIdx.x * blockDim.x + threadIdx.x;
    if (i >= P_SZ * N_NODES) return;
    int n = i & (N_NODES - 1);
    float v = mask[i];
    if (n + 1 < N_NODES) v = fmaxf(v, mask[i + 1]);
    if (n + 2 < N_NODES) v = fmaxf(v, mask[i + 2]);
    m_out[i] = v;
}

// ---------------------------------------------------------------------------
// Kernel 3: fused GEMM + relu + jump + mask scaling.
//   out[b,n,:] = relu( sum_f feat[b,n+f,:] @ W_f + edge[b,n,:] @ W_e + bias )
//   res = out + mean_f feat[b,n+f,:]
//   write m[b%4,n] * res  and  m[b%4,n] * out
// Block: 128 rows (one b, n0..n0+127) x 128 cols. 256 threads, 8x8 per thread
// (split as 4+4 rows/cols for conflict-free LDS.128).
// ---------------------------------------------------------------------------
__global__ __launch_bounds__(256, 2)
void fused_kernel(const float* __restrict__ feat,
                  const float* __restrict__ edge,
                  const float* __restrict__ W,
                  const float* __restrict__ bias,
                  const float* __restrict__ m_buf,
                  float* __restrict__ res_out,
                  float* __restrict__ outm_out) {
    __shared__ float As[16][132];   // [k][m], padded
    __shared__ float Bs[16][128];   // [k][n]

    const int tid = threadIdx.x;
    const int tx = tid & 15;
    const int ty = tid >> 4;
    const int n0 = blockIdx.x * 128;
    const int b  = blockIdx.y;

    ull acc[8][4];
#pragma unroll
    for (int i = 0; i < 8; i++)
#pragma unroll
        for (int j = 0; j < 4; j++) acc[i][j] = 0ULL;

    // 4 segments: f=0,1,2 over features (K=128 each), then edge (K=192)
    for (int seg = 0; seg < 4; ++seg) {
        const int nchunks = (seg < 3) ? (D_IN / 16) : (E_DIM / 16);
        for (int c = 0; c < nchunks; ++c) {
            const int k0 = c * 16;
            // --- load A tile (16 x 128, transposed into smem) ---
#pragma unroll
            for (int it = 0; it < 2; ++it) {
                int L = tid + it * 256;
                int mrow = L >> 2;
                int k4 = L & 3;
                float4 v = make_float4(0.f, 0.f, 0.f, 0.f);
                if (seg < 3) {
                    int row = n0 + mrow + seg;
                    if (row < N_NODES)
                        v = *(const float4*)&feat[(b * N_NODES + row) * D_IN + k0 + k4 * 4];
                } else {
                    int row = n0 + mrow;
                    v = *(const float4*)&edge[(b * N_NODES + row) * E_DIM + k0 + k4 * 4];
                }
                As[k4 * 4 + 0][mrow] = v.x;
                As[k4 * 4 + 1][mrow] = v.y;
                As[k4 * 4 + 2][mrow] = v.z;
                As[k4 * 4 + 3][mrow] = v.w;
            }
            // --- load B tile (16 x 128) ---
#pragma unroll
            for (int it = 0; it < 2; ++it) {
                int L = tid + it * 256;
                int kk = L >> 5;
                int n4 = L & 31;
                int wrow = (seg < 3) ? ((k0 + kk) * 3 + seg) : (K_FEAT + k0 + kk);
                *(float4*)&Bs[kk][n4 * 4] = *(const float4*)&W[wrow * D_MODEL + n4 * 4];
            }
            __syncthreads();
            // --- compute ---
#pragma unroll
            for (int kk = 0; kk < 16; ++kk) {
                float4 aLo = *(const float4*)&As[kk][ty * 4];
                float4 aHi = *(const float4*)&As[kk][64 + ty * 4];
                float4 bLo = *(const float4*)&Bs[kk][tx * 4];
                float4 bHi = *(const float4*)&Bs[kk][64 + tx * 4];
                ull b0 = pack2f(bLo.x, bLo.y);
                ull b1 = pack2f(bLo.z, bLo.w);
                ull b2 = pack2f(bHi.x, bHi.y);
                ull b3 = pack2f(bHi.z, bHi.w);
                float av[8] = {aLo.x, aLo.y, aLo.z, aLo.w, aHi.x, aHi.y, aHi.z, aHi.w};
#pragma unroll
                for (int i = 0; i < 8; ++i) {
                    ull ap = pack2(av[i]);
                    fma2(acc[i][0], ap, b0);
                    fma2(acc[i][1], ap, b1);
                    fma2(acc[i][2], ap, b2);
                    fma2(acc[i][3], ap, b3);
                }
            }
            __syncthreads();
        }
    }

    // --- epilogue ---
    const int p = b & (P_SZ - 1);
    float bv[8];
    {
        float4 t0 = *(const float4*)&bias[tx * 4];
        float4 t1 = *(const float4*)&bias[64 + tx * 4];
        bv[0] = t0.x; bv[1] = t0.y; bv[2] = t0.z; bv[3] = t0.w;
        bv[4] = t1.x; bv[5] = t1.y; bv[6] = t1.z; bv[7] = t1.w;
    }
    const float inv3 = 1.0f / 3.0f;

#pragma unroll
    for (int i = 0; i < 8; ++i) {
        int r = (i < 4) ? (ty * 4 + i) : (64 + ty * 4 + (i - 4));
        int n = n0 + r;
        float mval = m_buf[p * N_NODES + n];

        // jump = mean over window-3 of feat (zero padded past N)
        float jl[4] = {0.f, 0.f, 0.f, 0.f};
        float jh[4] = {0.f, 0.f, 0.f, 0.f};
#pragma unroll
        for (int f = 0; f < 3; ++f) {
            int row = n + f;
            if (row < N_NODES) {
                const float* fr = &feat[(b * N_NODES + row) * D_IN];
                float4 v0 = *(const float4*)&fr[tx * 4];
                float4 v1 = *(const float4*)&fr[64 + tx * 4];
                jl[0] += v0.x; jl[1] += v0.y; jl[2] += v0.z; jl[3] += v0.w;
                jh[0] += v1.x; jh[1] += v1.y; jh[2] += v1.z; jh[3] += v1.w;
            }
        }

        float2 a0 = unpack2(acc[i][0]);
        float2 a1 = unpack2(acc[i][1]);
        float2 a2 = unpack2(acc[i][2]);
        float2 a3 = unpack2(acc[i][3]);
        float o[8] = {a0.x, a0.y, a1.x, a1.y, a2.x, a2.y, a3.x, a3.y};

        float ov[8], rv[8];
#pragma unroll
        for (int j = 0; j < 4; ++j) {
            float out_v = fmaxf(o[j] + bv[j], 0.0f);
            ov[j] = mval * out_v;
            rv[j] = mval * (out_v + jl[j] * inv3);
        }
#pragma unroll
        for (int j = 0; j < 4; ++j) {
            float out_v = fmaxf(o[4 + j] + bv[4 + j], 0.0f);
            ov[4 + j] = mval * out_v;
            rv[4 + j] = mval * (out_v + jh[j] * inv3);
        }

        int base = (b * N_NODES + n) * D_MODEL;
        *(float4*)&outm_out[base + tx * 4]      = make_float4(ov[0], ov[1], ov[2], ov[3]);
        *(float4*)&outm_out[base + 64 + tx * 4] = make_float4(ov[4], ov[5], ov[6], ov[7]);
        *(float4*)&res_out[base + tx * 4]       = make_float4(rv[0], rv[1], rv[2], rv[3]);
        *(float4*)&res_out[base + 64 + tx * 4]  = make_float4(rv[4], rv[5], rv[6], rv[7]);
    }
}

// ---------------------------------------------------------------------------
// Launch: outputs packed as (adj, res_m, out_m, m) flattened fp32.
// ---------------------------------------------------------------------------
extern "C" void kernel_launch(void* const* d_in, const int* in_sizes, int n_in,
                              void* d_out, int out_size) {
    const float* adj  = (const float*)d_in[0];
    const float* feat = (const float*)d_in[1];
    const float* edge = (const float*)d_in[2];
    const float* mask = (const float*)d_in[3];
    const float* W    = (const float*)d_in[4];
    const float* bias = (const float*)d_in[5];
    float* out = (float*)d_out;

    const int ADJ_ELEMS = N_NODES * N_NODES;                 // 16777216
    const int RES_OFF   = ADJ_ELEMS;                         // 16777216
    const int OUTM_OFF  = RES_OFF + B_SZ * N_NODES * D_MODEL;  // 25165824
    const int M_OFF     = OUTM_OFF + B_SZ * N_NODES * D_MODEL; // 33554432

    // m must be ready before the fused kernel reads it (same stream => ordered)
    mask_kernel<<<(P_SZ * N_NODES + 255) / 256, 256>>>(mask, out + M_OFF);

    copy_kernel<<<(ADJ_ELEMS / 4 + 255) / 256, 256>>>(
        (const float4*)adj, (float4*)out, ADJ_ELEMS / 4);

    dim3 grid(N_NODES / 128, B_SZ);
    fused_kernel<<<grid, 256>>>(feat, edge, W, bias,
                                out + M_OFF, out + RES_OFF, out + OUTM_OFF);
}

// round 4
// speedup vs baseline: 1.8858x; 1.8858x over previous
#include <cuda_runtime.h>
#include <cuda_bf16.h>
#include <cstdint>

// ---------------- problem constants ----------------
#define N_NODES 4096
#define B_SZ 16
#define P_SZ 4
#define D_IN 128
#define E_DIM 192
#define D_MODEL 128

#define ADJ_ELEMS (N_NODES * N_NODES)
#define RES_OFF   ((size_t)ADJ_ELEMS)
#define OUTM_OFF  (RES_OFF + (size_t)B_SZ * N_NODES * D_MODEL)
#define M_OFF     (OUTM_OFF + (size_t)B_SZ * N_NODES * D_MODEL)

#define GEMM_BLOCKS 512
#define AUX_BLOCKS 512
#define NCHUNK 9              // 9 x K64 = 576

// smem: 4 tiles of 128 rows x 72 bf16 (64 data + 8 pad) = 18432 B each
#define AST 72
#define TILE_B (128 * AST * 2)          // 18432 bytes
#define OFF_AH 0
#define OFF_AL (TILE_B)
#define OFF_BH (2 * TILE_B)
#define OFF_BL (3 * TILE_B)
#define DYN_SMEM (4 * TILE_B)           // 73728

// prepacked W (hi/lo bf16, chunk-major [9][128 n][64 k])
__device__ __nv_bfloat16 g_Wpk_hi[NCHUNK * 128 * 64];
__device__ __nv_bfloat16 g_Wpk_lo[NCHUNK * 128 * 64];

// ---------------- helpers ----------------
__device__ __forceinline__ uint32_t smem_u32(const void* p) {
    uint32_t a;
    asm("{ .reg .u64 t; cvta.to.shared.u64 t, %1; cvt.u32.u64 %0, t; }" : "=r"(a) : "l"(p));
    return a;
}
__device__ __forceinline__ void ldm_x4(uint32_t* r, uint32_t addr) {
    asm volatile("ldmatrix.sync.aligned.m8n8.x4.shared.b16 {%0,%1,%2,%3}, [%4];"
        : "=r"(r[0]), "=r"(r[1]), "=r"(r[2]), "=r"(r[3]) : "r"(addr));
}
__device__ __forceinline__ void ldm_x2(uint32_t* r, uint32_t addr) {
    asm volatile("ldmatrix.sync.aligned.m8n8.x2.shared.b16 {%0,%1}, [%2];"
        : "=r"(r[0]), "=r"(r[1]) : "r"(addr));
}
__device__ __forceinline__ void mma_bf16(float* c, const uint32_t* a, const uint32_t* b) {
    asm volatile("mma.sync.aligned.m16n8k16.row.col.f32.bf16.bf16.f32 "
        "{%0,%1,%2,%3}, {%4,%5,%6,%7}, {%8,%9}, {%0,%1,%2,%3};"
        : "+f"(c[0]), "+f"(c[1]), "+f"(c[2]), "+f"(c[3])
        : "r"(a[0]), "r"(a[1]), "r"(a[2]), "r"(a[3]), "r"(b[0]), "r"(b[1]));
}
__device__ __forceinline__ uint32_t packbf2(__nv_bfloat16 a, __nv_bfloat16 b) {
    __nv_bfloat162 t(a, b);
    return *reinterpret_cast<uint32_t*>(&t);
}

// ---------------- prep: split + transpose + chunk-reorder W ----------------
__global__ void prep_w(const float* __restrict__ W) {
    int i = blockIdx.x * blockDim.x + threadIdx.x;
    if (i >= NCHUNK * 128 * 64) return;
    int c = i / (128 * 64);
    int e = i - c * (128 * 64);
    int n = e >> 6;
    int kk = e & 63;
    int seg, k0;
    if (c < 6) { seg = c >> 1; k0 = (c & 1) << 6; }
    else       { seg = 3;      k0 = (c - 6) << 6; }
    int k = k0 + kk;
    int wrow = (seg < 3) ? (k * 3 + seg) : (3 * D_IN + k);
    float v = W[wrow * D_MODEL + n];
    __nv_bfloat16 h = __float2bfloat16(v);
    g_Wpk_hi[i] = h;
    g_Wpk_lo[i] = __float2bfloat16(v - __bfloat162float(h));
}

// ---------------- mega kernel ----------------
__global__ __launch_bounds__(256, 2)
void mega_kernel(const float* __restrict__ adj,
                 const float* __restrict__ feat,
                 const float* __restrict__ edge,
                 const float* __restrict__ mask,
                 const float* __restrict__ bias,
                 float* __restrict__ out) {
    const int tid = threadIdx.x;

    if (blockIdx.x >= GEMM_BLOCKS) {
        // ---- aux: adj passthrough + m output ----
        int idx = (blockIdx.x - GEMM_BLOCKS) * 256 + tid;
        const float4* src = (const float4*)adj;
        float4* dst = (float4*)out;
        #pragma unroll 4
        for (int i = idx; i < ADJ_ELEMS / 4; i += AUX_BLOCKS * 256) dst[i] = src[i];
        for (int i = idx; i < P_SZ * N_NODES; i += AUX_BLOCKS * 256) {
            int n = i & (N_NODES - 1);
            float v = mask[i];
            if (n + 1 < N_NODES) v = fmaxf(v, mask[i + 1]);
            if (n + 2 < N_NODES) v = fmaxf(v, mask[i + 2]);
            out[M_OFF + i] = v;
        }
        return;
    }

    // ---- GEMM block ----
    extern __shared__ char smem[];
    const int b  = blockIdx.x >> 5;
    const int n0 = (blockIdx.x & 31) << 7;
    const int w    = tid >> 5;
    const int lane = tid & 31;
    const int mb = (w & 3) * 32;     // warp M base (rows of n-window)
    const int nb = (w >> 2) * 64;    // warp N base (d_model cols)

    __nv_bfloat16* sAh = (__nv_bfloat16*)(smem + OFF_AH);
    __nv_bfloat16* sAl = (__nv_bfloat16*)(smem + OFF_AL);
    __nv_bfloat16* sBh = (__nv_bfloat16*)(smem + OFF_BH);
    __nv_bfloat16* sBl = (__nv_bfloat16*)(smem + OFF_BL);
    const uint32_t sb   = smem_u32(smem);
    const uint32_t aHb = sb + OFF_AH, aLb = sb + OFF_AL;
    const uint32_t bHb = sb + OFF_BH, bLb = sb + OFF_BL;

    float acc[2][8][4];
    #pragma unroll
    for (int mf = 0; mf < 2; ++mf)
        #pragma unroll
        for (int nf = 0; nf < 8; ++nf)
            #pragma unroll
            for (int q = 0; q < 4; ++q) acc[mf][nf][q] = 0.f;

    for (int c = 0; c < NCHUNK; ++c) {
        int seg, k0;
        if (c < 6) { seg = c >> 1; k0 = (c & 1) << 6; }
        else       { seg = 3;      k0 = (c - 6) << 6; }

        // ---- A tile: 128 rows x 64 k fp32 -> bf16 hi/lo ----
        {
            const float* base;
            int ld;
            if (seg < 3) { base = feat + (size_t)b * N_NODES * D_IN + k0; ld = D_IN; }
            else         { base = edge + (size_t)b * N_NODES * E_DIM + k0; ld = E_DIM; }
            #pragma unroll
            for (int i = 0; i < 8; ++i) {
                int L = tid + (i << 8);
                int row = L >> 4, c4 = L & 15;
                int gr = n0 + row + (seg < 3 ? seg : 0);
                float4 v = make_float4(0.f, 0.f, 0.f, 0.f);
                if (seg >= 3 || gr < N_NODES)
                    v = *(const float4*)(base + (size_t)gr * ld + c4 * 4);
                __nv_bfloat16 h0 = __float2bfloat16(v.x), h1 = __float2bfloat16(v.y);
                __nv_bfloat16 h2 = __float2bfloat16(v.z), h3 = __float2bfloat16(v.w);
                int eo = row * AST + c4 * 4;
                *(uint2*)(sAh + eo) = make_uint2(packbf2(h0, h1), packbf2(h2, h3));
                __nv_bfloat16 l0 = __float2bfloat16(v.x - __bfloat162float(h0));
                __nv_bfloat16 l1 = __float2bfloat16(v.y - __bfloat162float(h1));
                __nv_bfloat16 l2 = __float2bfloat16(v.z - __bfloat162float(h2));
                __nv_bfloat16 l3 = __float2bfloat16(v.w - __bfloat162float(h3));
                *(uint2*)(sAl + eo) = make_uint2(packbf2(l0, l1), packbf2(l2, l3));
            }
        }
        // ---- B tile: copy prepacked chunk into padded layout ----
        {
            const uint4* bh = (const uint4*)g_Wpk_hi + c * 1024;
            const uint4* bl = (const uint4*)g_Wpk_lo + c * 1024;
            #pragma unroll
            for (int i = 0; i < 4; ++i) {
                int e = tid + (i << 8);
                int n = e >> 3, k8 = e & 7;
                int eo = n * AST + k8 * 8;
                *(uint4*)(sBh + eo) = bh[e];
                *(uint4*)(sBl + eo) = bl[e];
            }
        }
        __syncthreads();

        // ---- compute: 4 k-steps of 16 ----
        #pragma unroll
        for (int ks = 0; ks < 4; ++ks) {
            uint32_t ah[2][4], al[2][4];
            #pragma unroll
            for (int mf = 0; mf < 2; ++mf) {
                uint32_t off = (uint32_t)((mb + mf * 16 + (lane & 15)) * (AST * 2)
                                          + ks * 32 + (lane >> 4) * 16);
                ldm_x4(ah[mf], aHb + off);
                ldm_x4(al[mf], aLb + off);
            }
            #pragma unroll
            for (int nf = 0; nf < 8; ++nf) {
                uint32_t bh2[2], bl2[2];
                uint32_t boff = (uint32_t)((nb + nf * 8 + (lane & 7)) * (AST * 2)
                                           + ks * 32 + ((lane >> 3) & 1) * 16);
                ldm_x2(bh2, bHb + boff);
                ldm_x2(bl2, bLb + boff);
                mma_bf16(acc[0][nf], ah[0], bh2);
                mma_bf16(acc[1][nf], ah[1], bh2);
                mma_bf16(acc[0][nf], ah[0], bl2);
                mma_bf16(acc[1][nf], ah[1], bl2);
                mma_bf16(acc[0][nf], al[0], bh2);
                mma_bf16(acc[1][nf], al[1], bh2);
            }
        }
        __syncthreads();
    }

    // ---- epilogue (all in registers) ----
    const int p = b & (P_SZ - 1);
    const float inv3 = 1.0f / 3.0f;
    float2 bias2[8];
    #pragma unroll
    for (int nf = 0; nf < 8; ++nf)
        bias2[nf] = *(const float2*)(bias + nb + nf * 8 + (lane & 3) * 2);

    float* res  = out + RES_OFF;
    float* outm = out + OUTM_OFF;

    #pragma unroll
    for (int mf = 0; mf < 2; ++mf) {
        #pragma unroll
        for (int h = 0; h < 2; ++h) {
            int m = mb + mf * 16 + h * 8 + (lane >> 2);
            int n = n0 + m;
            float mv = mask[p * N_NODES + n];
            if (n + 1 < N_NODES) mv = fmaxf(mv, mask[p * N_NODES + n + 1]);
            if (n + 2 < N_NODES) mv = fmaxf(mv, mask[p * N_NODES + n + 2]);
            const size_t obase = ((size_t)(b * N_NODES + n)) * D_MODEL;
            const float* f0 = feat + ((size_t)(b * N_NODES + n)) * D_IN;
            #pragma unroll
            for (int nf = 0; nf < 8; ++nf) {
                int col = nb + nf * 8 + (lane & 3) * 2;
                float j0 = 0.f, j1 = 0.f;
                #pragma unroll
                for (int f = 0; f < 3; ++f) {
                    if (n + f < N_NODES) {
                        float2 v = *(const float2*)(f0 + (size_t)f * D_IN + col);
                        j0 += v.x; j1 += v.y;
                    }
                }
                float o0 = fmaxf(acc[mf][nf][h * 2 + 0] + bias2[nf].x, 0.f);
                float o1 = fmaxf(acc[mf][nf][h * 2 + 1] + bias2[nf].y, 0.f);
                *(float2*)(outm + obase + col) = make_float2(mv * o0, mv * o1);
                *(float2*)(res  + obase + col) =
                    make_float2(mv * (o0 + j0 * inv3), mv * (o1 + j1 * inv3));
            }
        }
    }
}

// ---------------- launch ----------------
extern "C" void kernel_launch(void* const* d_in, const int* in_sizes, int n_in,
                              void* d_out, int out_size) {
    const float* adj  = (const float*)d_in[0];
    const float* feat = (const float*)d_in[1];
    const float* edge = (const float*)d_in[2];
    const float* mask = (const float*)d_in[3];
    const float* W    = (const float*)d_in[4];
    const float* bias = (const float*)d_in[5];
    float* out = (float*)d_out;

    cudaFuncSetAttribute(mega_kernel, cudaFuncAttributeMaxDynamicSharedMemorySize, DYN_SMEM);

    prep_w<<<(NCHUNK * 128 * 64 + 255) / 256, 256>>>(W);
    mega_kernel<<<GEMM_BLOCKS + AUX_BLOCKS, 256, DYN_SMEM>>>(adj, feat, edge, mask, bias, out);
}